// round 15
// baseline (speedup 1.0000x reference)
#include <cuda_runtime.h>
#include <cstdint>

#define SEQ      512
#define BATCH    256
#define INSZ     64
#define HID      256
#define KTOT     320            // reordered contraction: [x 64 | local h 128 | peer h 128]
#define G        4
#define NTHREADS 512            // 16 warps: kw = w&7, jh = w>>3
#define KSPLIT   8
#define C2W      10             // ulonglong2 chunks per 40-float warp K-range

#define WH_FLOATS  (128 * KTOT)              // 40960 staging (init only)
#define RHS_FLOATS (2 * G * KTOT)            // 2560 double-buffered rows
#define RED2_U64   (KSPLIT * 2 * 128 * 2)    // 8 kw x 2 pair x 128 j x ulonglong2
#define SMEM_BYTES (WH_FLOATS*4 + RHS_FLOATS*4 + RED2_U64*8 + 128*4 + 16)

#define K_X      0
#define K_LOC    64
#define K_PEER   192

__device__ __forceinline__ void fma2(unsigned long long& d, unsigned long long a, unsigned long long b) {
    asm("fma.rn.f32x2 %0, %1, %2, %0;" : "+l"(d) : "l"(a), "l"(b));
}
__device__ __forceinline__ void add2(unsigned long long& d, unsigned long long a) {
    asm("add.rn.f32x2 %0, %0, %1;" : "+l"(d) : "l"(a));
}

__global__ void __cluster_dims__(2, 1, 1) __launch_bounds__(NTHREADS, 1)
rnn_persistent_kernel(const float* __restrict__ x,  const float* __restrict__ Wx,
                      const float* __restrict__ bx, const float* __restrict__ Wh,
                      const float* __restrict__ bh, float* __restrict__ out)
{
    extern __shared__ float sm[];
    float* wh_s  = sm;                                    // staging only
    float* rhs_s = sm + WH_FLOATS;                        // [2][G][320]
    ulonglong2* red2 = (ulonglong2*)(rhs_s + RHS_FLOATS); // [8][2][128] pairs
    float* bsum_s = (float*)(red2 + KSPLIT * 2 * 128);    // [128]
    unsigned long long* mbar = (unsigned long long*)(bsum_s + 128);  // [2]

    const int tid   = threadIdx.x;
    const int rank  = blockIdx.x & 1;
    const int b0    = (blockIdx.x >> 1) * G;
    const int jbase = rank * 128;
    const int pbase = 128 - jbase;
    const int w     = tid >> 5;
    const int l     = tid & 31;
    const int kw    = w & (KSPLIT - 1);
    const int jh    = w >> 3;
    const bool isB  = (kw >= 4);
    const int bw    = kw - 4;               // B-warp index 0..3

    // ---- init: stage weights in reordered K layout ----
    for (int idx = tid; idx < 128 * KTOT; idx += NTHREADS) {
        int j = idx / KTOT;
        int k = idx - j * KTOT;
        int jg = jbase + j;
        float v;
        if (k < K_LOC)        v = Wx[jg * INSZ + k];
        else if (k < K_PEER)  v = Wh[jg * HID + jbase + (k - K_LOC)];
        else                  v = Wh[jg * HID + pbase + (k - K_PEER)];
        wh_s[idx] = v;
    }
    if (tid < 128) bsum_s[tid] = bh[jbase + tid] + bx[jbase + tid];
    for (int idx = tid; idx < G * KTOT; idx += NTHREADS) {
        int b = idx / KTOT;
        int k = idx - b * KTOT;
        rhs_s[idx] = (k < K_LOC) ? x[(size_t)(b0 + b) * INSZ + k] : 0.f;
    }
    unsigned mb_s0 = (unsigned)__cvta_generic_to_shared(mbar);
    if (tid == 0) {
        asm volatile("mbarrier.init.shared.b64 [%0], 1;" :: "r"(mb_s0)     : "memory");
        asm volatile("mbarrier.init.shared.b64 [%0], 1;" :: "r"(mb_s0 + 8) : "memory");
    }
    __syncthreads();

    // ---- weights -> registers ----
    // A-warp (kw<4): K chunk [40kw, 40kw+40)  (x + local h only)
    // B-warp: 8 local floats [160+8bw, +8) then 32 peer floats [192+32bw, +32)
    unsigned long long wreg[2][2 * C2W];   // 20 u64 per j-row
    #pragma unroll
    for (int jj = 0; jj < 2; ++jj) {
        const float* rowp = wh_s + (jh * 64 + l + 32 * jj) * KTOT;
        if (!isB) {
            const unsigned long long* wr = (const unsigned long long*)(rowp + 40 * kw);
            #pragma unroll
            for (int p = 0; p < 20; ++p) wreg[jj][p] = wr[p];
        } else {
            const unsigned long long* wl = (const unsigned long long*)(rowp + 160 + 8 * bw);
            #pragma unroll
            for (int p = 0; p < 4; ++p) wreg[jj][p] = wl[p];
            const unsigned long long* wp = (const unsigned long long*)(rowp + K_PEER + 32 * bw);
            #pragma unroll
            for (int p = 0; p < 16; ++p) wreg[jj][4 + p] = wp[p];
        }
    }
    asm volatile("barrier.cluster.arrive.aligned;" ::: "memory");
    asm volatile("barrier.cluster.wait.aligned;"   ::: "memory");

    const int jr = tid & 127;       // reducer: j index
    const int pr = tid >> 7;        // reducer: b-pair (tid<256 only)
    const int bb = tid >> 6;        // x prefetch batch lane (tid<256)
    const int xi = tid & 63;
    int ph0 = 0, ph1 = 0;

    float* outt     = out;
    float* out_last = out + (size_t)SEQ * BATCH * HID;

    for (int t = 0; t < SEQ; ++t) {
        const int cur = t & 1;
        const int nxt = cur ^ 1;
        const unsigned mb_cur = mb_s0 + cur * 8;
        const unsigned mb_nxt = mb_s0 + nxt * 8;

        if (tid == 0 && t + 1 < SEQ)
            asm volatile("mbarrier.arrive.expect_tx.shared.b64 _, [%0], %1;"
                         :: "r"(mb_nxt), "r"(2048u) : "memory");

        float xv = 0.f;
        if (t + 1 < SEQ && tid < G * INSZ)
            xv = x[(size_t)(t + 1) * BATCH * INSZ + (size_t)(b0 + bb) * INSZ + xi];

        unsigned long long acc[2][4];
        #pragma unroll
        for (int jj = 0; jj < 2; ++jj)
            #pragma unroll
            for (int b = 0; b < 4; ++b) acc[jj][b] = 0ull;

        const float* rbase = rhs_s + cur * (G * KTOT);

        if (!isB) {
            // ---- A GEMM: 10 chunks over [40kw, +40), no wait ----
            const ulonglong2* rc2 = (const ulonglong2*)(rbase + 40 * kw);
            #pragma unroll
            for (int it = 0; it < C2W; ++it) {
                #pragma unroll
                for (int b = 0; b < 4; ++b) {
                    ulonglong2 hv = rc2[b * (KTOT / 4) + it];
                    #pragma unroll
                    for (int jj = 0; jj < 2; ++jj) {
                        fma2(acc[jj][b], wreg[jj][2 * it],     hv.x);
                        fma2(acc[jj][b], wreg[jj][2 * it + 1], hv.y);
                    }
                }
            }
        } else {
            // ---- B GEMM: 2 local chunks first (absorbs peer skew) ----
            const ulonglong2* rl = (const ulonglong2*)(rbase + 160 + 8 * bw);
            #pragma unroll
            for (int it = 0; it < 2; ++it) {
                #pragma unroll
                for (int b = 0; b < 4; ++b) {
                    ulonglong2 hv = rl[b * (KTOT / 4) + it];
                    #pragma unroll
                    for (int jj = 0; jj < 2; ++jj) {
                        fma2(acc[jj][b], wreg[jj][2 * it],     hv.x);
                        fma2(acc[jj][b], wreg[jj][2 * it + 1], hv.y);
                    }
                }
            }
            // wait for peer h of step t-1
            if (t > 0) {
                const int p = cur ? ph1 : ph0;
                asm volatile(
                    "{\n\t.reg .pred P;\n\t"
                    "WAITL%=:\n\t"
                    "mbarrier.try_wait.parity.acquire.cta.shared::cta.b64 P, [%0], %1, 0x989680;\n\t"
                    "@P bra DONE%=;\n\t"
                    "bra WAITL%=;\n\t"
                    "DONE%=:\n\t}"
                    :: "r"(mb_cur), "r"(p) : "memory");
            }
            // ---- 8 peer chunks over [192+32bw, +32) ----
            const ulonglong2* rp = (const ulonglong2*)(rbase + K_PEER + 32 * bw);
            #pragma unroll
            for (int it = 0; it < 8; ++it) {
                #pragma unroll
                for (int b = 0; b < 4; ++b) {
                    ulonglong2 hv = rp[b * (KTOT / 4) + it];
                    #pragma unroll
                    for (int jj = 0; jj < 2; ++jj) {
                        fma2(acc[jj][b], wreg[jj][4 + 2 * it],     hv.x);
                        fma2(acc[jj][b], wreg[jj][4 + 2 * it + 1], hv.y);
                    }
                }
            }
        }
        if (t > 0) { if (cur) ph1 ^= 1; else ph0 ^= 1; }

        // ---- paired stash: 2 STS.128 per jj, lane stride 16B => conflict-free ----
        #pragma unroll
        for (int jj = 0; jj < 2; ++jj) {
            const int j = jh * 64 + l + 32 * jj;
            ulonglong2 v01; v01.x = acc[jj][0]; v01.y = acc[jj][1];
            ulonglong2 v23; v23.x = acc[jj][2]; v23.y = acc[jj][3];
            red2[(kw * 2 + 0) * 128 + j] = v01;
            red2[(kw * 2 + 1) * 128 + j] = v23;
        }
        __syncthreads();

        // ---- paired reduce: 256 threads, 2 outputs each (b=2pr, 2pr+1) ----
        float* rnext = rhs_s + nxt * (G * KTOT);
        if (tid < 256) {
            const ulonglong2* q = red2 + pr * 128 + jr;
            ulonglong2 s = q[0];
            #pragma unroll
            for (int ww = 1; ww < KSPLIT; ++ww) {
                ulonglong2 qq = q[(size_t)ww * 256];
                add2(s.x, qq.x); add2(s.y, qq.y);
            }
            const float bsum = bsum_s[jr];
            float lo0, hi0, lo1, hi1;
            asm("mov.b64 {%0, %1}, %2;" : "=f"(lo0), "=f"(hi0) : "l"(s.x));
            asm("mov.b64 {%0, %1}, %2;" : "=f"(lo1), "=f"(hi1) : "l"(s.y));
            float z0 = lo0 + hi0 + bsum;
            float z1 = lo1 + hi1 + bsum;
            float e0, e1, r0, r1;
            asm("ex2.approx.f32 %0, %1;" : "=f"(e0) : "f"(z0 * 2.885390081777927f));
            asm("ex2.approx.f32 %0, %1;" : "=f"(e1) : "f"(z1 * 2.885390081777927f));
            asm("rcp.approx.f32 %0, %1;" : "=f"(r0) : "f"(e0 + 1.0f));
            asm("rcp.approx.f32 %0, %1;" : "=f"(r1) : "f"(e1 + 1.0f));
            float h0 = fmaf(-2.0f, r0, 1.0f);
            float h1 = fmaf(-2.0f, r1, 1.0f);

            const int bA = 2 * pr, bB = 2 * pr + 1;
            // remote first (longest latency)
            if (t + 1 < SEQ) {
                unsigned ra_mb;
                asm("mapa.shared::cluster.u32 %0, %1, %2;" : "=r"(ra_mb) : "r"(mb_nxt), "r"(rank ^ 1));
                unsigned laA = (unsigned)__cvta_generic_to_shared(&rnext[bA * KTOT + K_PEER + jr]);
                unsigned laB = (unsigned)__cvta_generic_to_shared(&rnext[bB * KTOT + K_PEER + jr]);
                unsigned raA, raB;
                asm("mapa.shared::cluster.u32 %0, %1, %2;" : "=r"(raA) : "r"(laA), "r"(rank ^ 1));
                asm("mapa.shared::cluster.u32 %0, %1, %2;" : "=r"(raB) : "r"(laB), "r"(rank ^ 1));
                asm volatile("st.async.shared::cluster.mbarrier::complete_tx::bytes.b32 [%0], %1, [%2];"
                             :: "r"(raA), "f"(h0), "r"(ra_mb) : "memory");
                asm volatile("st.async.shared::cluster.mbarrier::complete_tx::bytes.b32 [%0], %1, [%2];"
                             :: "r"(raB), "f"(h1), "r"(ra_mb) : "memory");
            }
            rnext[bA * KTOT + K_LOC + jr] = h0;
            rnext[bB * KTOT + K_LOC + jr] = h1;

            const int jg = jbase + jr;
            outt[(size_t)(b0 + bA) * HID + jg] = h0;
            outt[(size_t)(b0 + bB) * HID + jg] = h1;
            if (t == SEQ - 1) {
                out_last[(size_t)(b0 + bA) * HID + jg] = h0;
                out_last[(size_t)(b0 + bB) * HID + jg] = h1;
            }
            if (t + 1 < SEQ) rnext[bb * KTOT + K_X + xi] = xv;  // stage next x
        }
        outt += BATCH * HID;

        __syncthreads();   // local rnext (h, x) visible to all warps for step t+1
    }
}

extern "C" void kernel_launch(void* const* d_in, const int* in_sizes, int n_in,
                              void* d_out, int out_size) {
    const float* x  = (const float*)d_in[0];
    const float* Wx = (const float*)d_in[1];
    const float* bx = (const float*)d_in[2];
    const float* Wh = (const float*)d_in[3];
    const float* bh = (const float*)d_in[4];
    float* out = (float*)d_out;
    (void)in_sizes; (void)n_in; (void)out_size;

    cudaFuncSetAttribute(rnn_persistent_kernel,
                         cudaFuncAttributeMaxDynamicSharedMemorySize, SMEM_BYTES);
    rnn_persistent_kernel<<<128, NTHREADS, SMEM_BYTES>>>(x, Wx, bx, Wh, bh, out);
}

// round 16
// speedup vs baseline: 1.0524x; 1.0524x over previous
#include <cuda_runtime.h>
#include <cstdint>

#define SEQ      512
#define BATCH    256
#define INSZ     64
#define HID      256
#define KTOT     320            // reordered contraction: [x 64 | local h 128 | peer h 128]
#define G        4
#define NTHREADS 512            // 16 warps: kw = w&7, jh = w>>3
#define KSPLIT   8
#define LOC_F    24             // local floats per kw chunk (8*24 = 192 = x + local h)
#define PEER_F   16             // peer floats per kw chunk (8*16 = 128 = peer h)
#define LOC_C    6              // ulonglong2 chunks local
#define PEER_C   4              // ulonglong2 chunks peer

#define WH_FLOATS  (128 * KTOT)              // 40960 staging (init only)
#define RHS_FLOATS (2 * G * KTOT)            // 2560 double-buffered rows
#define RED_U64    (KSPLIT * G * 128)        // 4096  red[kw][b][j]
#define SMEM_BYTES (WH_FLOATS*4 + RHS_FLOATS*4 + RED_U64*8 + 128*4 + 16)

#define K_X      0
#define K_LOC    64
#define K_PEER   192

__device__ __forceinline__ void fma2(unsigned long long& d, unsigned long long a, unsigned long long b) {
    asm("fma.rn.f32x2 %0, %1, %2, %0;" : "+l"(d) : "l"(a), "l"(b));
}
__device__ __forceinline__ void add2(unsigned long long& d, unsigned long long a) {
    asm("add.rn.f32x2 %0, %0, %1;" : "+l"(d) : "l"(a));
}

__global__ void __cluster_dims__(2, 1, 1) __launch_bounds__(NTHREADS, 1)
rnn_persistent_kernel(const float* __restrict__ x,  const float* __restrict__ Wx,
                      const float* __restrict__ bx, const float* __restrict__ Wh,
                      const float* __restrict__ bh, float* __restrict__ out)
{
    extern __shared__ float sm[];
    float* wh_s  = sm;                                    // staging only
    float* rhs_s = sm + WH_FLOATS;                        // [2][G][320]
    unsigned long long* red_s = (unsigned long long*)(rhs_s + RHS_FLOATS); // [8][4][128]
    float* bsum_s = (float*)(red_s + RED_U64);            // [128]
    unsigned long long* mbar = (unsigned long long*)(bsum_s + 128);        // [2]

    const int tid   = threadIdx.x;
    const int rank  = blockIdx.x & 1;
    const int b0    = (blockIdx.x >> 1) * G;
    const int jbase = rank * 128;
    const int pbase = 128 - jbase;
    const int w     = tid >> 5;
    const int l     = tid & 31;
    const int kw    = w & (KSPLIT - 1);
    const int jh    = w >> 3;

    // ---- init: stage weights in reordered K layout ----
    for (int idx = tid; idx < 128 * KTOT; idx += NTHREADS) {
        int j = idx / KTOT;
        int k = idx - j * KTOT;
        int jg = jbase + j;
        float v;
        if (k < K_LOC)        v = Wx[jg * INSZ + k];
        else if (k < K_PEER)  v = Wh[jg * HID + jbase + (k - K_LOC)];
        else                  v = Wh[jg * HID + pbase + (k - K_PEER)];
        wh_s[idx] = v;
    }
    if (tid < 128) bsum_s[tid] = bh[jbase + tid] + bx[jbase + tid];
    for (int idx = tid; idx < G * KTOT; idx += NTHREADS) {
        int b = idx / KTOT;
        int k = idx - b * KTOT;
        rhs_s[idx] = (k < K_LOC) ? x[(size_t)(b0 + b) * INSZ + k] : 0.f;
    }
    unsigned mb_s0 = (unsigned)__cvta_generic_to_shared(mbar);
    if (tid == 0) {
        asm volatile("mbarrier.init.shared.b64 [%0], 1;" :: "r"(mb_s0)     : "memory");
        asm volatile("mbarrier.init.shared.b64 [%0], 1;" :: "r"(mb_s0 + 8) : "memory");
    }
    __syncthreads();

    // ---- weights -> registers (BALANCED): rows j = jh*64 + l + 32*jj,
    //      local K [24kw, +24), peer K [192+16kw, +16) ----
    unsigned long long wreg[2][2 * (LOC_C + PEER_C)];     // 20 u64 per j-row
    #pragma unroll
    for (int jj = 0; jj < 2; ++jj) {
        const float* rowp = wh_s + (jh * 64 + l + 32 * jj) * KTOT;
        const unsigned long long* wl = (const unsigned long long*)(rowp + LOC_F * kw);
        #pragma unroll
        for (int p = 0; p < 2 * LOC_C; ++p) wreg[jj][p] = wl[p];
        const unsigned long long* wp = (const unsigned long long*)(rowp + K_PEER + PEER_F * kw);
        #pragma unroll
        for (int p = 0; p < 2 * PEER_C; ++p) wreg[jj][2 * LOC_C + p] = wp[p];
    }
    asm volatile("barrier.cluster.arrive.aligned;" ::: "memory");
    asm volatile("barrier.cluster.wait.aligned;"   ::: "memory");

    const int jr = tid & 127;       // epilogue: local j (coalesced, conflict-free)
    const int br = tid >> 7;        // epilogue: batch index
    const int bb = tid >> 6;        // x prefetch: batch lane (tid<256)
    const int xi = tid & 63;        // x prefetch: input index
    int ph0 = 0, ph1 = 0;

    float* outt     = out;
    float* out_last = out + (size_t)SEQ * BATCH * HID;

    for (int t = 0; t < SEQ; ++t) {
        const int cur = t & 1;
        const int nxt = cur ^ 1;
        const unsigned mb_cur = mb_s0 + cur * 8;
        const unsigned mb_nxt = mb_s0 + nxt * 8;

        if (tid == 0 && t + 1 < SEQ)
            asm volatile("mbarrier.arrive.expect_tx.shared.b64 _, [%0], %1;"
                         :: "r"(mb_nxt), "r"(2048u) : "memory");

        float xv = 0.f;
        if (t + 1 < SEQ && tid < G * INSZ)
            xv = x[(size_t)(t + 1) * BATCH * INSZ + (size_t)(b0 + bb) * INSZ + xi];

        unsigned long long acc[2][4];
        #pragma unroll
        for (int jj = 0; jj < 2; ++jj)
            #pragma unroll
            for (int b = 0; b < 4; ++b) acc[jj][b] = 0ull;

        const float* rbase = rhs_s + cur * (G * KTOT);

        // ---- local part: 6 chunks over [24kw, +24) — no wait needed ----
        {
            const ulonglong2* rl = (const ulonglong2*)(rbase + LOC_F * kw);
            #pragma unroll
            for (int it = 0; it < LOC_C; ++it) {
                #pragma unroll
                for (int b = 0; b < 4; ++b) {
                    ulonglong2 hv = rl[b * (KTOT / 4) + it];
                    #pragma unroll
                    for (int jj = 0; jj < 2; ++jj) {
                        fma2(acc[jj][b], wreg[jj][2 * it],     hv.x);
                        fma2(acc[jj][b], wreg[jj][2 * it + 1], hv.y);
                    }
                }
            }
        }

        // ---- wait for peer h of step t-1 (all warps; local work absorbed skew) ----
        if (t > 0) {
            const int p = cur ? ph1 : ph0;
            asm volatile(
                "{\n\t.reg .pred P;\n\t"
                "WAITL%=:\n\t"
                "mbarrier.try_wait.parity.acquire.cta.shared::cta.b64 P, [%0], %1, 0x989680;\n\t"
                "@P bra DONE%=;\n\t"
                "bra WAITL%=;\n\t"
                "DONE%=:\n\t}"
                :: "r"(mb_cur), "r"(p) : "memory");
            if (cur) ph1 ^= 1; else ph0 ^= 1;
        }

        // ---- peer part: 4 chunks over [192+16kw, +16) ----
        {
            const ulonglong2* rp = (const ulonglong2*)(rbase + K_PEER + PEER_F * kw);
            #pragma unroll
            for (int it = 0; it < PEER_C; ++it) {
                #pragma unroll
                for (int b = 0; b < 4; ++b) {
                    ulonglong2 hv = rp[b * (KTOT / 4) + it];
                    #pragma unroll
                    for (int jj = 0; jj < 2; ++jj) {
                        fma2(acc[jj][b], wreg[jj][2 * LOC_C + 2 * it],     hv.x);
                        fma2(acc[jj][b], wreg[jj][2 * LOC_C + 2 * it + 1], hv.y);
                    }
                }
            }
        }

        // ---- stash partials: red[kw][b][j], lane stride 1 u64 => conflict-free ----
        #pragma unroll
        for (int jj = 0; jj < 2; ++jj) {
            const int j = jh * 64 + l + 32 * jj;
            #pragma unroll
            for (int b = 0; b < 4; ++b)
                red_s[(size_t)(kw * 4 + b) * 128 + j] = acc[jj][b];
        }
        __syncthreads();

        // ---- reduce(8) + bias + tanh + exchange + output: ONE output per thread ----
        float* rnext = rhs_s + nxt * (G * KTOT);
        {
            const unsigned long long* q = red_s + (size_t)br * 128 + jr;
            unsigned long long s2 = q[0];
            #pragma unroll
            for (int ww = 1; ww < KSPLIT; ++ww) add2(s2, q[(size_t)ww * 512]);
            float lo, hi;
            asm("mov.b64 {%0, %1}, %2;" : "=f"(lo), "=f"(hi) : "l"(s2));
            float z = lo + hi + bsum_s[jr];
            // tanh(z) = 1 - 2/(exp2(2z*log2e)+1)
            float ex;  asm("ex2.approx.f32 %0, %1;" : "=f"(ex)  : "f"(z * 2.885390081777927f));
            float rcp; asm("rcp.approx.f32 %0, %1;" : "=f"(rcp) : "f"(ex + 1.0f));
            float h = fmaf(-2.0f, rcp, 1.0f);

            // remote first (longest latency): our h lands in peer's PEER region
            if (t + 1 < SEQ) {
                unsigned la = (unsigned)__cvta_generic_to_shared(&rnext[br * KTOT + K_PEER + jr]);
                unsigned ra, ra_mb;
                asm("mapa.shared::cluster.u32 %0, %1, %2;" : "=r"(ra)    : "r"(la),     "r"(rank ^ 1));
                asm("mapa.shared::cluster.u32 %0, %1, %2;" : "=r"(ra_mb) : "r"(mb_nxt), "r"(rank ^ 1));
                asm volatile("st.async.shared::cluster.mbarrier::complete_tx::bytes.b32 [%0], %1, [%2];"
                             :: "r"(ra), "f"(h), "r"(ra_mb) : "memory");
            }
            rnext[br * KTOT + K_LOC + jr] = h;              // our h -> our LOCAL region

            const int jg = jbase + jr;
            const int bg = b0 + br;
            outt[(size_t)bg * HID + jg] = h;                // coalesced 128B
            if (t == SEQ - 1) out_last[(size_t)bg * HID + jg] = h;
        }
        if (t + 1 < SEQ && tid < G * INSZ)
            rnext[bb * KTOT + K_X + xi] = xv;               // stage next x
        outt += BATCH * HID;

        __syncthreads();   // local rnext (h, x) visible to all warps for step t+1
    }
}

extern "C" void kernel_launch(void* const* d_in, const int* in_sizes, int n_in,
                              void* d_out, int out_size) {
    const float* x  = (const float*)d_in[0];
    const float* Wx = (const float*)d_in[1];
    const float* bx = (const float*)d_in[2];
    const float* Wh = (const float*)d_in[3];
    const float* bh = (const float*)d_in[4];
    float* out = (float*)d_out;
    (void)in_sizes; (void)n_in; (void)out_size;

    cudaFuncSetAttribute(rnn_persistent_kernel,
                         cudaFuncAttributeMaxDynamicSharedMemorySize, SMEM_BYTES);
    rnn_persistent_kernel<<<128, NTHREADS, SMEM_BYTES>>>(x, Wx, bx, Wh, bh, out);
}